// round 2
// baseline (speedup 1.0000x reference)
#include <cuda_runtime.h>
#include <cstdint>

// Problem constants
#define BD 64      // input dim
#define H1 128
#define H2 32
#define G 8
#define F 8
#define E 4
#define AH 8       // attention dim
#define NH 2       // heads
#define OUTD 2

// ---- packed f32x2 helpers (Blackwell FFMA2) ----
__device__ __forceinline__ unsigned long long pk2(float lo, float hi) {
    unsigned long long r;
    asm("mov.b64 %0, {%1, %2};" : "=l"(r) : "f"(lo), "f"(hi));
    return r;
}
__device__ __forceinline__ void upk2(unsigned long long a, float& lo, float& hi) {
    asm("mov.b64 {%0, %1}, %2;" : "=f"(lo), "=f"(hi) : "l"(a));
}
__device__ __forceinline__ void fma2(unsigned long long& d, unsigned long long a, unsigned long long b) {
    asm("fma.rn.f32x2 %0, %1, %2, %0;" : "+l"(d) : "l"(a), "l"(b));
}
__device__ __forceinline__ unsigned long long add2(unsigned long long a, unsigned long long b) {
    unsigned long long r;
    asm("add.rn.f32x2 %0, %1, %2;" : "=l"(r) : "l"(a), "l"(b));
    return r;
}

// Shared memory layout (floats)
#define SW1_OFF   0            // [128][66] w1 transposed, padded
#define SW2_OFF   8448         // [128][32]
#define SB1_OFF   (SW2_OFF + 4096)
#define SB2_OFF   (SB1_OFF + 128)
#define SMEAN_OFF (SB2_OFF + 32)
#define SINV_OFF  (SMEAN_OFF + 64)
#define SENW_OFF  (SINV_OFF + 64)     // 256
#define SENB_OFF  (SENW_OFF + 256)    // 32
#define SM_OFF    (SENB_OFF + 32)     // 2*16
#define SU_OFF    (SM_OFF + 32)       // 8
#define SV_OFF    (SU_OFF + 8)        // 8
#define SC_OFF    (SV_OFF + 8)        // 2
#define SDW_OFF   (SC_OFF + 2)        // 192
#define SDB_OFF   (SDW_OFF + 192)     // 2
#define SMEM_FLOATS (SDB_OFF + 2)
#define SMEM_BYTES  (SMEM_FLOATS * 4)

#define TPB 256

extern "C" __global__ void __launch_bounds__(TPB)
ggat_kernel(const float* __restrict__ x,
            const float* __restrict__ norm_mean,
            const float* __restrict__ norm_std,
            const float* __restrict__ w1,
            const float* __restrict__ b1,
            const float* __restrict__ w2,
            const float* __restrict__ b2,
            const float* __restrict__ encw,
            const float* __restrict__ encb,
            const float* __restrict__ srcw,
            const float* __restrict__ srcb,
            const float* __restrict__ dstw,
            const float* __restrict__ dstb,
            const float* __restrict__ decw,
            const float* __restrict__ decb,
            float* __restrict__ out,
            int n)
{
    extern __shared__ float sm[];
    float* sw1   = sm + SW1_OFF;
    float* sw2   = sm + SW2_OFF;
    float* sb1   = sm + SB1_OFF;
    float* sb2   = sm + SB2_OFF;
    float* smean = sm + SMEAN_OFF;
    float* sinv  = sm + SINV_OFF;
    float* senw  = sm + SENW_OFF;
    float* senb  = sm + SENB_OFF;
    float* sM    = sm + SM_OFF;
    float* su    = sm + SU_OFF;
    float* sv    = sm + SV_OFF;
    float* sc    = sm + SC_OFF;
    float* sdw   = sm + SDW_OFF;
    float* sdb   = sm + SDB_OFF;

    const int tid = threadIdx.x;

    // ------------- stage weights -------------
    for (int idx = tid; idx < BD * H1; idx += TPB) {
        int d = idx >> 7;      // row in w1 (input dim)
        int j = idx & 127;     // col (hidden unit)
        sw1[j * 66 + d] = w1[idx];
    }
    for (int idx = tid; idx < H1 * H2; idx += TPB) sw2[idx] = w2[idx];
    if (tid < H1) sb1[tid] = b1[tid];
    if (tid < H2) sb2[tid] = b2[tid];
    if (tid < BD) {
        smean[tid] = norm_mean[tid];
        sinv[tid]  = 1.0f / (norm_std[tid] + 1e-8f);
    }
    for (int idx = tid; idx < G * F * E; idx += TPB) senw[idx] = encw[idx];
    if (tid < G * E) senb[tid] = encb[tid];
    if (tid < (H2 + 2 * G * E) * OUTD) sdw[tid] = decw[tid];
    if (tid < OUTD) sdb[tid] = decb[tid];

    // Precompute per-head attention reduction:
    //   score[g][k] = (h_g S + bs) . (h_k D + bd) / sqrt(A)
    //              = h_g M h_k^T + u.h_g + v.h_k + c   (all pre-scaled)
    if (tid < NH) {
        const int hh = tid;
        const float invs = rsqrtf((float)AH);
        for (int e = 0; e < E; e++) {
            for (int e2 = 0; e2 < E; e2++) {
                float m = 0.f;
                for (int a = 0; a < AH; a++)
                    m = fmaf(srcw[e * (NH * AH) + hh * AH + a],
                             dstw[e2 * (NH * AH) + hh * AH + a], m);
                sM[hh * 16 + e * 4 + e2] = m * invs;
            }
        }
        for (int e = 0; e < E; e++) {
            float uu = 0.f, vv = 0.f;
            for (int a = 0; a < AH; a++) {
                uu = fmaf(srcw[e * (NH * AH) + hh * AH + a], dstb[hh * AH + a], uu);
                vv = fmaf(dstw[e * (NH * AH) + hh * AH + a], srcb[hh * AH + a], vv);
            }
            su[hh * 4 + e] = uu * invs;
            sv[hh * 4 + e] = vv * invs;
        }
        float cc = 0.f;
        for (int a = 0; a < AH; a++)
            cc = fmaf(srcb[hh * AH + a], dstb[hh * AH + a], cc);
        sc[hh] = cc * invs;
    }
    __syncthreads();

    const int elem = blockIdx.x * TPB + tid;
    if (elem >= n) return;

    // ------------- load x row as f32x2 pairs -------------
    unsigned long long xp[32];
    const float4* xr = reinterpret_cast<const float4*>(x + (size_t)elem * BD);
#pragma unroll
    for (int i = 0; i < 16; i++) {
        float4 v = __ldg(xr + i);
        xp[2 * i]     = pk2(v.x, v.y);
        xp[2 * i + 1] = pk2(v.z, v.w);
    }

    // ------------- MLP: 64 -> 128 -> 32 (fused, packed FFMA2) -------------
    unsigned long long h2p[16];
#pragma unroll
    for (int i = 0; i < 16; i++) h2p[i] = pk2(sb2[2 * i], sb2[2 * i + 1]);

#pragma unroll 4
    for (int j = 0; j < H1; j++) {
        const unsigned long long* w1r =
            reinterpret_cast<const unsigned long long*>(sw1 + j * 66);
        unsigned long long a0 = 0ull, a1 = 0ull, a2 = 0ull, a3 = 0ull;
#pragma unroll
        for (int i = 0; i < 8; i++) {
            fma2(a0, xp[4 * i + 0], w1r[4 * i + 0]);
            fma2(a1, xp[4 * i + 1], w1r[4 * i + 1]);
            fma2(a2, xp[4 * i + 2], w1r[4 * i + 2]);
            fma2(a3, xp[4 * i + 3], w1r[4 * i + 3]);
        }
        unsigned long long s01 = add2(add2(a0, a1), add2(a2, a3));
        float lo, hi;
        upk2(s01, lo, hi);
        float h1 = lo + hi + sb1[j];
        h1 = fmaxf(h1, 0.0f);
        unsigned long long h1p = pk2(h1, h1);
        const unsigned long long* w2r =
            reinterpret_cast<const unsigned long long*>(sw2 + j * H2);
#pragma unroll
        for (int i = 0; i < 16; i++) fma2(h2p[i], h1p, w2r[i]);
    }

    float xh[H2];
#pragma unroll
    for (int i = 0; i < 16; i++) {
        float a, b;
        upk2(h2p[i], a, b);
        xh[2 * i]     = fmaxf(a, 0.f);
        xh[2 * i + 1] = fmaxf(b, 0.f);
    }

    // ------------- per-group encoders -------------
    float hv[G * E];
#pragma unroll
    for (int g = 0; g < G; g++) {
        float xn[F];
#pragma unroll
        for (int i = 0; i < 4; i++) {
            float a, b;
            upk2(xp[g * 4 + i], a, b);
            int d = g * 8 + 2 * i;
            xn[2 * i]     = (a - smean[d]) * sinv[d];
            xn[2 * i + 1] = (b - smean[d + 1]) * sinv[d + 1];
        }
#pragma unroll
        for (int e = 0; e < E; e++) {
            float acc = senb[g * E + e];
#pragma unroll
            for (int f = 0; f < F; f++)
                acc = fmaf(xn[f], senw[g * (F * E) + f * E + e], acc);
            hv[g * E + e] = fmaxf(acc, 0.f);
        }
    }

    // ------------- GAT multi-head attention over G nodes -------------
    float att[G * E];
#pragma unroll
    for (int i = 0; i < G * E; i++) att[i] = 0.f;

#pragma unroll
    for (int hh = 0; hh < NH; hh++) {
        float t[G * E];
        float sg[G], dk[G];
#pragma unroll
        for (int g = 0; g < G; g++) {
#pragma unroll
            for (int e2 = 0; e2 < E; e2++) {
                float acc = 0.f;
#pragma unroll
                for (int e = 0; e < E; e++)
                    acc = fmaf(hv[g * E + e], sM[hh * 16 + e * 4 + e2], acc);
                t[g * E + e2] = acc;
            }
            float a1 = 0.f, a2 = 0.f;
#pragma unroll
            for (int e = 0; e < E; e++) {
                a1 = fmaf(hv[g * E + e], su[hh * 4 + e], a1);
                a2 = fmaf(hv[g * E + e], sv[hh * 4 + e], a2);
            }
            sg[g] = a1;
            dk[g] = a2;
        }
        const float cc = sc[hh];
#pragma unroll
        for (int g = 0; g < G; g++) {
            float s[G];
            float mx = -1e30f;
#pragma unroll
            for (int k = 0; k < G; k++) {
                float acc = sg[g] + dk[k] + cc;
#pragma unroll
                for (int e2 = 0; e2 < E; e2++)
                    acc = fmaf(t[g * E + e2], hv[k * E + e2], acc);
                s[k] = acc;
                mx = fmaxf(mx, acc);
            }
            float p[G];
            float sum = 0.f;
#pragma unroll
            for (int k = 0; k < G; k++) {
                p[k] = __expf(s[k] - mx);
                sum += p[k];
            }
            float inv = 1.0f / sum;
#pragma unroll
            for (int k = 0; k < G; k++) {
                float pk = p[k] * inv;
#pragma unroll
                for (int e = 0; e < E; e++)
                    att[g * E + e] = fmaf(pk, hv[k * E + e], att[g * E + e]);
            }
        }
    }

    // ------------- decoder: feats[96] @ dec_w[96][2] + dec_b -------------
    float o0 = sdb[0], o1 = sdb[1];
#pragma unroll
    for (int i = 0; i < H2; i++) {
        o0 = fmaf(xh[i], sdw[i * 2 + 0], o0);
        o1 = fmaf(xh[i], sdw[i * 2 + 1], o1);
    }
#pragma unroll
    for (int i = 0; i < G * E; i++) {
        o0 = fmaf(hv[i], sdw[(H2 + i) * 2 + 0], o0);
        o1 = fmaf(hv[i], sdw[(H2 + i) * 2 + 1], o1);
    }
#pragma unroll
    for (int i = 0; i < G * E; i++) {
        o0 = fmaf(att[i], sdw[(H2 + G * E + i) * 2 + 0], o0);
        o1 = fmaf(att[i], sdw[(H2 + G * E + i) * 2 + 1], o1);
    }

    float2 r;
    r.x = o0;
    r.y = o1;
    reinterpret_cast<float2*>(out)[elem] = r;
}

extern "C" void kernel_launch(void* const* d_in, const int* in_sizes, int n_in,
                              void* d_out, int out_size)
{
    const float* x     = (const float*)d_in[0];
    const float* mean_ = (const float*)d_in[1];
    const float* std_  = (const float*)d_in[2];
    const float* w1    = (const float*)d_in[3];
    const float* b1    = (const float*)d_in[4];
    const float* w2    = (const float*)d_in[5];
    const float* b2    = (const float*)d_in[6];
    const float* encw  = (const float*)d_in[7];
    const float* encb  = (const float*)d_in[8];
    const float* srcw  = (const float*)d_in[9];
    const float* srcb  = (const float*)d_in[10];
    const float* dstw  = (const float*)d_in[11];
    const float* dstb  = (const float*)d_in[12];
    const float* decw  = (const float*)d_in[13];
    const float* decb  = (const float*)d_in[14];
    float* out = (float*)d_out;

    int n = in_sizes[0] / BD;

    cudaFuncSetAttribute(ggat_kernel,
                         cudaFuncAttributeMaxDynamicSharedMemorySize, SMEM_BYTES);

    dim3 grid((n + TPB - 1) / TPB);
    ggat_kernel<<<grid, TPB, SMEM_BYTES>>>(x, mean_, std_, w1, b1, w2, b2,
                                           encw, encb, srcw, srcb, dstw, dstb,
                                           decw, decb, out, n);
}